// round 2
// baseline (speedup 1.0000x reference)
#include <cuda_runtime.h>

#define B_ 32
#define K_ 64
#define W_ 100
#define H_ 150
#define G_ 450
#define KW_ 6400
#define ALPHA_ 0.2f
#define THRES_ 0.0002f

// ---------------- scratch (__device__ globals; no allocation allowed) ----------------
__device__ float g_Wx[B_*K_*W_];                 // (b*64+s)*100+w
__device__ float g_cx[B_*K_*W_];                 // cause_x
__device__ float g_linT[W_*W_];                  // [i][w]
__device__ float g_glwihT[W_*G_];                // [i][g]
__device__ float2 g_glwhhP[(H_/2)*G_];           // packed pairs over i: [(i/2)][g] = (w_i, w_{i+1})
__device__ float g_muT[H_*H_];                   // [i][o]
__device__ float g_stdT[H_*H_];
__device__ float g_netwihT[K_*W_*G_];            // [k][i][g]
__device__ float g_netwhhT[K_*H_*G_];            // [k][i][g]
__device__ float g_gxg[K_*B_*G_];                // (s*32+b)*450+g
__device__ float g_hl[B_*H_];
__device__ float g_z[B_*H_];
__device__ float g_gxnet[K_*B_*K_*G_];           // (k*2048 + b*64 + s)*450 + g   (236MB)

// ---------------- helpers ----------------
__device__ __forceinline__ unsigned long long pk2(float a, float b){
    unsigned long long r;
    asm("mov.b64 %0, {%1,%2};" : "=l"(r) : "f"(a), "f"(b));
    return r;
}
__device__ __forceinline__ void fma2(unsigned long long &d, unsigned long long a, unsigned long long b){
    asm("fma.rn.f32x2 %0, %1, %2, %0;" : "+l"(d) : "l"(a), "l"(b));
}
__device__ __forceinline__ float2 up2(unsigned long long v){
    float a, b;
    asm("mov.b64 {%0,%1}, %2;" : "=f"(a), "=f"(b) : "l"(v));
    float2 r; r.x = a; r.y = b; return r;
}
__device__ __forceinline__ float sigf(float x){
    return __fdividef(1.f, 1.f + __expf(-x));
}
__device__ __forceinline__ float tanhf_(float x){
    float e = __expf(2.f * x);
    return 1.f - __fdividef(2.f, e + 1.f);
}

// ---------------- prep: transposes / packing ----------------
__global__ void k_prep(const float* lin_w, const float* gl_wih, const float* gl_whh,
                       const float* mu_w, const float* std_w,
                       const float* net_wih, const float* net_whh)
{
    int tid = blockIdx.x * blockDim.x + threadIdx.x;
    int stride = gridDim.x * blockDim.x;
    for (int e = tid; e < W_*W_; e += stride){
        int w = e / W_, i = e % W_;
        g_linT[i*W_ + w] = lin_w[e];
    }
    for (int e = tid; e < G_*W_; e += stride){
        int g = e / W_, i = e % W_;
        g_glwihT[i*G_ + g] = gl_wih[e];
    }
    for (int e = tid; e < (H_/2)*G_; e += stride){
        int i2 = e / G_, g = e % G_;
        float2 v;
        v.x = gl_whh[g*H_ + 2*i2];
        v.y = gl_whh[g*H_ + 2*i2 + 1];
        g_glwhhP[e] = v;
    }
    for (int e = tid; e < H_*H_; e += stride){
        int o = e / H_, i = e % H_;
        g_muT[i*H_ + o]  = mu_w[e];
        g_stdT[i*H_ + o] = std_w[e];
    }
    for (int e = tid; e < K_*G_*W_; e += stride){
        int k = e / (G_*W_); int rem = e % (G_*W_);
        int g = rem / W_, i = rem % W_;
        g_netwihT[k*(W_*G_) + i*G_ + g] = net_wih[e];
    }
    for (int e = tid; e < K_*G_*H_; e += stride){
        int k = e / (G_*H_); int rem = e % (G_*H_);
        int g = rem / H_, i = rem % H_;
        g_netwhhT[k*(H_*G_) + i*G_ + g] = net_whh[e];
    }
}

// ---------------- K1: Wx = x @ lin_w^T + lin_b ----------------
__global__ void k_wx(const float* __restrict__ x, const float* __restrict__ lin_b)
{
    __shared__ float xs[W_];
    int row = blockIdx.x;            // b*64+s, 2048 rows
    int t = threadIdx.x;             // 128
    if (t < W_) xs[t] = x[row*W_ + t];
    __syncthreads();
    if (t < W_){
        float acc = lin_b[t];
        #pragma unroll 4
        for (int i = 0; i < W_; i++) acc += xs[i] * g_linT[i*W_ + t];
        g_Wx[row*W_ + t] = acc;
    }
}

// ---------------- K2: attention scalar + cause_x ----------------
__global__ void k_attn(const float* __restrict__ y, const float* __restrict__ a,
                       const float* __restrict__ bias)
{
    int b = blockIdx.x >> 6;
    int k = blockIdx.x & 63;
    const float a0 = a[0], a1 = a[1];
    const float yb = a0 * y[b*K_ + k];
    const float* vrow = g_Wx + b*KW_;
    const float* brow = bias + k*KW_;
    int t = threadIdx.x;             // 256

    __shared__ float red[256];

    // pass 1: max
    float m = -3.4e38f;
    for (int j = t; j < KW_; j += 256){
        float e = yb + a1*vrow[j] + brow[j];
        e = e > 0.f ? e : ALPHA_*e;
        m = fmaxf(m, e);
    }
    red[t] = m; __syncthreads();
    for (int o = 128; o > 0; o >>= 1){
        if (t < o) red[t] = fmaxf(red[t], red[t+o]);
        __syncthreads();
    }
    float M = red[0]; __syncthreads();

    // pass 2: sumexp
    float ssum = 0.f;
    for (int j = t; j < KW_; j += 256){
        float e = yb + a1*vrow[j] + brow[j];
        e = e > 0.f ? e : ALPHA_*e;
        ssum += __expf(e - M);
    }
    red[t] = ssum; __syncthreads();
    for (int o = 128; o > 0; o >>= 1){
        if (t < o) red[t] += red[t+o];
        __syncthreads();
    }
    float S = red[0]; __syncthreads();

    // threshold in e-space: p >= THRES  <=>  e >= M + ln(THRES*S)
    float T = M + __logf(THRES_ * S);

    float acc = 0.f;
    for (int j = t; j < KW_; j += 256){
        float v = vrow[j];
        float e = yb + a1*v + brow[j];
        e = e > 0.f ? e : ALPHA_*e;
        if (e >= T) acc += v;
    }
    red[t] = acc; __syncthreads();
    for (int o = 128; o > 0; o >>= 1){
        if (t < o) red[t] += red[t+o];
        __syncthreads();
    }
    float sbk = red[0];

    if (t < W_){
        int row = b*K_ + k;
        g_cx[row*W_ + t] = g_Wx[row*W_ + t] + sbk;
    }
}

// ---------------- K3: gx for global GRU ----------------
__global__ void k_gxg(const float* __restrict__ gl_bih)
{
    int s = blockIdx.x >> 5;
    int b = blockIdx.x & 31;
    __shared__ float cx[W_];
    int t = threadIdx.x;             // 512
    if (t < W_) cx[t] = g_cx[(b*K_ + s)*W_ + t];
    __syncthreads();
    if (t < G_){
        float acc = gl_bih[t];
        #pragma unroll 4
        for (int i = 0; i < W_; i++) acc += cx[i] * g_glwihT[i*G_ + t];
        g_gxg[(s*B_ + b)*G_ + t] = acc;
    }
}

// ---------------- K4: global GRU (32 CTAs, one per batch) ----------------
__global__ void k_gru_gl(const float* __restrict__ gl_bhh)
{
    int b = blockIdx.x;
    int t = threadIdx.x;             // 512
    __shared__ __align__(16) float h_sh[152];
    __shared__ float gh_sh[G_];
    if (t < 152) h_sh[t] = 0.f;
    float bhh = (t < G_) ? gl_bhh[t] : 0.f;
    __syncthreads();

    for (int s = 0; s < 64; s++){
        if (t < G_){
            unsigned long long acc = 0ull;
            const unsigned long long* wp = (const unsigned long long*)g_glwhhP;
            const unsigned long long* hp = (const unsigned long long*)h_sh;
            #pragma unroll 5
            for (int i2 = 0; i2 < H_/2; i2++){
                fma2(acc, wp[i2*G_ + t], hp[i2]);
            }
            float2 v = up2(acc);
            gh_sh[t] = v.x + v.y + bhh;
        }
        __syncthreads();
        if (t < H_){
            const float* gx = g_gxg + (s*B_ + b)*G_;
            float r  = sigf(gx[t]        + gh_sh[t]);
            float zz = sigf(gx[H_ + t]   + gh_sh[H_ + t]);
            float n  = tanhf_(gx[2*H_+t] + r * gh_sh[2*H_ + t]);
            h_sh[t] = (1.f - zz)*n + zz*h_sh[t];
        }
        __syncthreads();
    }
    if (t < H_) g_hl[b*H_ + t] = h_sh[t];
}

// ---------------- K5: z = mu + exp(0.5 logvar) * noise ----------------
__global__ void k_z(const float* __restrict__ mu_b, const float* __restrict__ std_b,
                    const float* __restrict__ z_noise)
{
    int b = blockIdx.x, t = threadIdx.x;   // 160
    __shared__ float hs[152];
    if (t < H_) hs[t] = g_hl[b*H_ + t];
    __syncthreads();
    if (t < H_){
        float mu = mu_b[t], lv = std_b[t];
        #pragma unroll 2
        for (int i = 0; i < H_; i++){
            float h = hs[i];
            mu += h * g_muT[i*H_ + t];
            lv += h * g_stdT[i*H_ + t];
        }
        g_z[b*H_ + t] = mu + __expf(0.5f*lv) * z_noise[b*H_ + t];
    }
}

// ---------------- K6: gx for all 64 net GRUs (big GEMM, f32x2) ----------------
__global__ void k_gxnet(const float* __restrict__ net_bih)
{
    int bid = blockIdx.x;            // 8192
    int k = bid >> 7;
    int r0 = (bid & 127) * 16;       // row block (row = b*64+s)
    __shared__ __align__(16) float A_sh[W_*16];
    int t = threadIdx.x;             // 512
    for (int e = t; e < 16*W_; e += 512){
        int rr = e / W_, i = e % W_;
        A_sh[i*16 + rr] = g_Wx[(r0 + rr)*W_ + i];
    }
    __syncthreads();
    if (t < G_){
        const float* wrow = g_netwihT + k*(W_*G_);
        unsigned long long acc[8];
        #pragma unroll
        for (int p = 0; p < 8; p++) acc[p] = 0ull;
        #pragma unroll 2
        for (int i = 0; i < W_; i++){
            float w = wrow[i*G_ + t];
            unsigned long long w2 = pk2(w, w);
            const ulonglong2* hp = (const ulonglong2*)&A_sh[i*16];
            ulonglong2 q0 = hp[0], q1 = hp[1], q2 = hp[2], q3 = hp[3];
            fma2(acc[0], w2, q0.x); fma2(acc[1], w2, q0.y);
            fma2(acc[2], w2, q1.x); fma2(acc[3], w2, q1.y);
            fma2(acc[4], w2, q2.x); fma2(acc[5], w2, q2.y);
            fma2(acc[6], w2, q3.x); fma2(acc[7], w2, q3.y);
        }
        float bi = net_bih[k*G_ + t];
        #pragma unroll
        for (int p = 0; p < 8; p++){
            float2 v = up2(acc[p]);
            g_gxnet[(k*2048 + r0 + 2*p    )*G_ + t] = v.x + bi;
            g_gxnet[(k*2048 + r0 + 2*p + 1)*G_ + t] = v.y + bi;
        }
    }
}

// ---------------- K7: 64 net GRU recurrences (128 CTAs: k x 16-batch) ----------------
__global__ void k_gru_net(const float* __restrict__ net_bhh, float* __restrict__ out)
{
    int k  = blockIdx.x >> 1;
    int b0 = (blockIdx.x & 1) * 16;
    int t = threadIdx.x;             // 512
    __shared__ __align__(16) float h_sh[H_*16];    // [j][bb]
    __shared__ float gh_sh[16*G_];                 // [bb][g]

    for (int e = t; e < H_*16; e += 512){
        int j = e / 16, bb = e % 16;
        h_sh[e] = g_z[(b0 + bb)*H_ + j];
    }
    __syncthreads();

    const float* wrow = g_netwhhT + k*(H_*G_);
    float bhh = (t < G_) ? net_bhh[k*G_ + t] : 0.f;

    for (int s = 0; s < 64; s++){
        if (t < G_){
            unsigned long long acc[8];
            #pragma unroll
            for (int p = 0; p < 8; p++) acc[p] = 0ull;
            #pragma unroll 2
            for (int i = 0; i < H_; i++){
                float w = wrow[i*G_ + t];
                unsigned long long w2 = pk2(w, w);
                const ulonglong2* hp = (const ulonglong2*)&h_sh[i*16];
                ulonglong2 q0 = hp[0], q1 = hp[1], q2 = hp[2], q3 = hp[3];
                fma2(acc[0], w2, q0.x); fma2(acc[1], w2, q0.y);
                fma2(acc[2], w2, q1.x); fma2(acc[3], w2, q1.y);
                fma2(acc[4], w2, q2.x); fma2(acc[5], w2, q2.y);
                fma2(acc[6], w2, q3.x); fma2(acc[7], w2, q3.y);
            }
            #pragma unroll
            for (int p = 0; p < 8; p++){
                float2 v = up2(acc[p]);
                gh_sh[(2*p  )*G_ + t] = v.x + bhh;
                gh_sh[(2*p+1)*G_ + t] = v.y + bhh;
            }
        }
        __syncthreads();
        for (int e = t; e < 16*H_; e += 512){
            int bb = e / H_, j = e % H_;
            const float* gx = g_gxnet + (k*2048 + (b0 + bb)*K_ + s)*G_;
            float ghr = gh_sh[bb*G_ + j];
            float ghz = gh_sh[bb*G_ + H_ + j];
            float ghn = gh_sh[bb*G_ + 2*H_ + j];
            float r  = sigf(gx[j] + ghr);
            float zz = sigf(gx[H_ + j] + ghz);
            float n  = tanhf_(gx[2*H_ + j] + r*ghn);
            float hold = h_sh[j*16 + bb];
            h_sh[j*16 + bb] = (1.f - zz)*n + zz*hold;
        }
        __syncthreads();
    }

    for (int e = t; e < 16*H_; e += 512){
        int bb = e / H_, j = e % H_;
        out[(b0 + bb)*(K_*H_) + k*H_ + j] = h_sh[j*16 + bb];
    }
}

// ---------------- launch ----------------
extern "C" void kernel_launch(void* const* d_in, const int* in_sizes, int n_in,
                              void* d_out, int out_size)
{
    const float* x       = (const float*)d_in[0];
    const float* y       = (const float*)d_in[1];
    const float* z_noise = (const float*)d_in[2];
    const float* lin_w   = (const float*)d_in[3];
    const float* lin_b   = (const float*)d_in[4];
    const float* a       = (const float*)d_in[5];
    const float* bias    = (const float*)d_in[6];
    const float* gl_wih  = (const float*)d_in[7];
    const float* gl_whh  = (const float*)d_in[8];
    const float* gl_bih  = (const float*)d_in[9];
    const float* gl_bhh  = (const float*)d_in[10];
    const float* mu_w    = (const float*)d_in[11];
    const float* mu_b    = (const float*)d_in[12];
    const float* std_w   = (const float*)d_in[13];
    const float* std_b   = (const float*)d_in[14];
    const float* net_wih = (const float*)d_in[15];
    const float* net_whh = (const float*)d_in[16];
    const float* net_bih = (const float*)d_in[17];
    const float* net_bhh = (const float*)d_in[18];
    float* out = (float*)d_out;

    k_prep<<<1024, 256>>>(lin_w, gl_wih, gl_whh, mu_w, std_w, net_wih, net_whh);
    k_wx<<<B_*K_, 128>>>(x, lin_b);
    k_gxnet<<<K_*128, 512>>>(net_bih);          // needs only Wx
    k_attn<<<B_*K_, 256>>>(y, a, bias);
    k_gxg<<<K_*B_, 512>>>(gl_bih);
    k_gru_gl<<<B_, 512>>>(gl_bhh);
    k_z<<<B_, 160>>>(mu_b, std_b, z_noise);
    k_gru_net<<<K_*2, 512>>>(net_bhh, out);
}

// round 3
// speedup vs baseline: 1.1439x; 1.1439x over previous
#include <cuda_runtime.h>

#define B_ 32
#define K_ 64
#define W_ 100
#define H_ 150
#define G_ 450
#define KW_ 6400
#define ALPHA_ 0.2f
#define THRES_ 0.0002f

// ---------------- scratch ----------------
__device__ float g_Wx[B_*K_*W_];
__device__ float g_cx[B_*K_*W_];
__device__ float g_linT[W_*W_];
__device__ float g_glwihT[W_*G_];
__device__ float2 g_glwhhP[(H_/2)*G_];
__device__ float g_muT[H_*H_];
__device__ float g_stdT[H_*H_];
__device__ float g_netwihT[K_*W_*G_];            // [k][i][g]
__device__ float g_netwhhT[K_*H_*G_];            // [k][i][g]
__device__ float g_gxg[K_*B_*G_];
__device__ float g_hl[B_*H_];
__device__ float g_z[B_*H_];
__device__ float g_gxnet[K_*B_*K_*G_];           // (k*2048 + b*64 + s)*450 + g

// ---------------- helpers ----------------
__device__ __forceinline__ unsigned long long pk2(float a, float b){
    unsigned long long r;
    asm("mov.b64 %0, {%1,%2};" : "=l"(r) : "f"(a), "f"(b));
    return r;
}
__device__ __forceinline__ void fma2(unsigned long long &d, unsigned long long a, unsigned long long b){
    asm("fma.rn.f32x2 %0, %1, %2, %0;" : "+l"(d) : "l"(a), "l"(b));
}
__device__ __forceinline__ float2 up2(unsigned long long v){
    float a, b;
    asm("mov.b64 {%0,%1}, %2;" : "=f"(a), "=f"(b) : "l"(v));
    float2 r; r.x = a; r.y = b; return r;
}
__device__ __forceinline__ float sigf(float x){ return __fdividef(1.f, 1.f + __expf(-x)); }
__device__ __forceinline__ float tanhf_(float x){
    float e = __expf(2.f * x);
    return 1.f - __fdividef(2.f, e + 1.f);
}
__device__ __forceinline__ unsigned cta_rank(){
    unsigned r; asm("mov.u32 %0, %%cluster_ctarank;" : "=r"(r)); return r;
}
__device__ __forceinline__ void cluster_sync(){
    asm volatile("barrier.cluster.arrive.aligned;" ::: "memory");
    asm volatile("barrier.cluster.wait.aligned;"  ::: "memory");
}
__device__ __forceinline__ void st_peer_f32(float* local_ptr, unsigned peer, float v){
    unsigned la = (unsigned)__cvta_generic_to_shared(local_ptr);
    unsigned ra;
    asm volatile("mapa.shared::cluster.u32 %0, %1, %2;" : "=r"(ra) : "r"(la), "r"(peer));
    asm volatile("st.shared::cluster.f32 [%0], %1;" :: "r"(ra), "f"(v) : "memory");
}

// ---------------- prep ----------------
__global__ void k_prep(const float* lin_w, const float* gl_wih, const float* gl_whh,
                       const float* mu_w, const float* std_w,
                       const float* net_wih, const float* net_whh)
{
    int tid = blockIdx.x * blockDim.x + threadIdx.x;
    int stride = gridDim.x * blockDim.x;
    for (int e = tid; e < W_*W_; e += stride){
        int w = e / W_, i = e % W_;
        g_linT[i*W_ + w] = lin_w[e];
    }
    for (int e = tid; e < G_*W_; e += stride){
        int g = e / W_, i = e % W_;
        g_glwihT[i*G_ + g] = gl_wih[e];
    }
    for (int e = tid; e < (H_/2)*G_; e += stride){
        int i2 = e / G_, g = e % G_;
        float2 v;
        v.x = gl_whh[g*H_ + 2*i2];
        v.y = gl_whh[g*H_ + 2*i2 + 1];
        g_glwhhP[e] = v;
    }
    for (int e = tid; e < H_*H_; e += stride){
        int o = e / H_, i = e % H_;
        g_muT[i*H_ + o]  = mu_w[e];
        g_stdT[i*H_ + o] = std_w[e];
    }
    for (int e = tid; e < K_*G_*W_; e += stride){
        int k = e / (G_*W_); int rem = e % (G_*W_);
        int g = rem / W_, i = rem % W_;
        g_netwihT[k*(W_*G_) + i*G_ + g] = net_wih[e];
    }
    for (int e = tid; e < K_*G_*H_; e += stride){
        int k = e / (G_*H_); int rem = e % (G_*H_);
        int g = rem / H_, i = rem % H_;
        g_netwhhT[k*(H_*G_) + i*G_ + g] = net_whh[e];
    }
}

// ---------------- K1: Wx ----------------
__global__ void k_wx(const float* __restrict__ x, const float* __restrict__ lin_b)
{
    __shared__ float xs[W_];
    int row = blockIdx.x;
    int t = threadIdx.x;
    if (t < W_) xs[t] = x[row*W_ + t];
    __syncthreads();
    if (t < W_){
        float acc = lin_b[t];
        #pragma unroll 4
        for (int i = 0; i < W_; i++) acc += xs[i] * g_linT[i*W_ + t];
        g_Wx[row*W_ + t] = acc;
    }
}

// ---------------- K2: attention (single data pass, register cache) ----------------
__global__ __launch_bounds__(256) void k_attn(const float* __restrict__ y,
                       const float* __restrict__ a, const float* __restrict__ bias)
{
    int b = blockIdx.x >> 6;
    int k = blockIdx.x & 63;
    const float a0 = a[0], a1 = a[1];
    const float yb = a0 * y[b*K_ + k];
    const float* vrow = g_Wx + b*KW_;
    const float* brow = bias + k*KW_;
    int t = threadIdx.x;             // 256

    __shared__ float red[256];

    float e_loc[25], v_loc[25];
    float m = -3.4e38f;
    #pragma unroll
    for (int jj = 0; jj < 25; jj++){
        int j = t + jj*256;
        float v = vrow[j];
        float e = yb + a1*v + brow[j];
        e = e > 0.f ? e : ALPHA_*e;
        e_loc[jj] = e; v_loc[jj] = v;
        m = fmaxf(m, e);
    }
    red[t] = m; __syncthreads();
    for (int o = 128; o > 0; o >>= 1){
        if (t < o) red[t] = fmaxf(red[t], red[t+o]);
        __syncthreads();
    }
    float M = red[0]; __syncthreads();

    float ssum = 0.f;
    #pragma unroll
    for (int jj = 0; jj < 25; jj++) ssum += __expf(e_loc[jj] - M);
    red[t] = ssum; __syncthreads();
    for (int o = 128; o > 0; o >>= 1){
        if (t < o) red[t] += red[t+o];
        __syncthreads();
    }
    float S = red[0]; __syncthreads();

    float T = M + __logf(THRES_ * S);

    float acc = 0.f;
    #pragma unroll
    for (int jj = 0; jj < 25; jj++) if (e_loc[jj] >= T) acc += v_loc[jj];
    red[t] = acc; __syncthreads();
    for (int o = 128; o > 0; o >>= 1){
        if (t < o) red[t] += red[t+o];
        __syncthreads();
    }
    float sbk = red[0];

    if (t < W_){
        int row = b*K_ + k;
        g_cx[row*W_ + t] = g_Wx[row*W_ + t] + sbk;
    }
}

// ---------------- K3: gx for global GRU ----------------
__global__ void k_gxg(const float* __restrict__ gl_bih)
{
    int s = blockIdx.x >> 5;
    int b = blockIdx.x & 31;
    __shared__ float cx[W_];
    int t = threadIdx.x;             // 512
    if (t < W_) cx[t] = g_cx[(b*K_ + s)*W_ + t];
    __syncthreads();
    if (t < G_){
        float acc = gl_bih[t];
        #pragma unroll 4
        for (int i = 0; i < W_; i++) acc += cx[i] * g_glwihT[i*G_ + t];
        g_gxg[(s*B_ + b)*G_ + t] = acc;
    }
}

// ---------------- K4: global GRU ----------------
__global__ void k_gru_gl(const float* __restrict__ gl_bhh)
{
    int b = blockIdx.x;
    int t = threadIdx.x;             // 512
    __shared__ __align__(16) float h_sh[152];
    __shared__ float gh_sh[G_];
    if (t < 152) h_sh[t] = 0.f;
    float bhh = (t < G_) ? gl_bhh[t] : 0.f;
    __syncthreads();

    for (int s = 0; s < 64; s++){
        if (t < G_){
            unsigned long long acc = 0ull;
            const unsigned long long* wp = (const unsigned long long*)g_glwhhP;
            const unsigned long long* hp = (const unsigned long long*)h_sh;
            #pragma unroll 5
            for (int i2 = 0; i2 < H_/2; i2++){
                fma2(acc, wp[i2*G_ + t], hp[i2]);
            }
            float2 v = up2(acc);
            gh_sh[t] = v.x + v.y + bhh;
        }
        __syncthreads();
        if (t < H_){
            const float* gx = g_gxg + (s*B_ + b)*G_;
            float r  = sigf(gx[t]        + gh_sh[t]);
            float zz = sigf(gx[H_ + t]   + gh_sh[H_ + t]);
            float n  = tanhf_(gx[2*H_+t] + r * gh_sh[2*H_ + t]);
            h_sh[t] = (1.f - zz)*n + zz*h_sh[t];
        }
        __syncthreads();
    }
    if (t < H_) g_hl[b*H_ + t] = h_sh[t];
}

// ---------------- K5: z ----------------
__global__ void k_z(const float* __restrict__ mu_b, const float* __restrict__ std_b,
                    const float* __restrict__ z_noise)
{
    int b = blockIdx.x, t = threadIdx.x;   // 160
    __shared__ float hs[152];
    if (t < H_) hs[t] = g_hl[b*H_ + t];
    __syncthreads();
    if (t < H_){
        float mu = mu_b[t], lv = std_b[t];
        #pragma unroll 2
        for (int i = 0; i < H_; i++){
            float h = hs[i];
            mu += h * g_muT[i*H_ + t];
            lv += h * g_stdT[i*H_ + t];
        }
        g_z[b*H_ + t] = mu + __expf(0.5f*lv) * z_noise[b*H_ + t];
    }
}

// ---------------- K6: gxnet GEMM, weights resident in smem ----------------
// 128 CTAs: k = bid>>1, row-half = bid&1 (1024 rows each), 64 blocks of 16 rows.
#define GXN_SMEM_FLOATS (45000 + 1600)
__global__ __launch_bounds__(512, 1) void k_gxnet(const float* __restrict__ net_bih)
{
    extern __shared__ __align__(16) float sm6[];
    float* w_sh = sm6;               // [i][450], 45000 floats
    float* A_sh = sm6 + 45000;       // [i][16],  1600 floats
    int k    = blockIdx.x >> 1;
    int half = blockIdx.x & 1;
    int t = threadIdx.x;             // 512

    const float* wsrc = g_netwihT + k*(W_*G_);
    for (int e = t; e < W_*G_; e += 512) w_sh[e] = wsrc[e];

    float bi = (t < G_) ? net_bih[k*G_ + t] : 0.f;

    int row_base = half*1024;
    for (int rb = 0; rb < 64; rb++){
        int r0 = row_base + rb*16;
        const float* Ab = g_Wx + r0*W_;
        // prefetch A block (16 rows x 100, contiguous) into regs
        float a0 = Ab[t];
        float a1 = Ab[t + 512];
        float a2 = Ab[t + 1024];
        float a3 = (t < 64) ? Ab[t + 1536] : 0.f;
        __syncthreads();             // prev compute done (and w_sh on rb==0)
        {
            int e = t;          A_sh[(e%W_)*16 + e/W_] = a0;
            e = t + 512;        A_sh[(e%W_)*16 + e/W_] = a1;
            e = t + 1024;       A_sh[(e%W_)*16 + e/W_] = a2;
            if (t < 64){ e = t + 1536; A_sh[(e%W_)*16 + e/W_] = a3; }
        }
        __syncthreads();

        if (t < G_){
            unsigned long long acc[8];
            #pragma unroll
            for (int p = 0; p < 8; p++) acc[p] = 0ull;
            #pragma unroll 2
            for (int i = 0; i < W_; i++){
                float w = w_sh[i*G_ + t];
                unsigned long long w2 = pk2(w, w);
                const ulonglong2* hp = (const ulonglong2*)&A_sh[i*16];
                ulonglong2 q0 = hp[0], q1 = hp[1], q2 = hp[2], q3 = hp[3];
                fma2(acc[0], w2, q0.x); fma2(acc[1], w2, q0.y);
                fma2(acc[2], w2, q1.x); fma2(acc[3], w2, q1.y);
                fma2(acc[4], w2, q2.x); fma2(acc[5], w2, q2.y);
                fma2(acc[6], w2, q3.x); fma2(acc[7], w2, q3.y);
            }
            #pragma unroll
            for (int p = 0; p < 8; p++){
                float2 v = up2(acc[p]);
                g_gxnet[(k*2048 + r0 + 2*p    )*G_ + t] = v.x + bi;
                g_gxnet[(k*2048 + r0 + 2*p + 1)*G_ + t] = v.y + bi;
            }
        }
    }
}

// ---------------- K7: net GRUs — cluster(2) gate-aligned G-split, smem weights ----
// 64 clusters x 2 CTAs. CTA hf owns gate-local cols jj in [hf*75, hf*75+75) of each
// gate -> 225 cols, 135KB weights. All 32 batches. h double-buffered, halves
// exchanged via DSMEM store + barrier.cluster.
#define GRN_W   0
#define GRN_H0  33752
#define GRN_H1  (33752 + 4800)
#define GRN_GH  (33752 + 9600)
#define GRN_BHH (GRN_GH + 32*226)
#define GRN_SMEM_FLOATS (GRN_BHH + 232)

__global__ __launch_bounds__(512, 1) __cluster_dims__(2,1,1)
void k_gru_net(const float* __restrict__ net_bhh, float* __restrict__ out)
{
    extern __shared__ __align__(16) float sm7[];
    int k = blockIdx.x >> 1;
    unsigned hf = cta_rank();
    unsigned peer = hf ^ 1u;
    int t = threadIdx.x;             // 512

    float* w_sh   = sm7 + GRN_W;     // [i][225]
    float* gh_sh  = sm7 + GRN_GH;    // [bb][226]
    float* bhh_sh = sm7 + GRN_BHH;

    // stage weights (one time): col c -> global gate col
    const float* wsrc = g_netwhhT + k*(H_*G_);
    for (int e = t; e < H_*225; e += 512){
        int i = e / 225, c = e - i*225;
        int gcol = (c/75)*H_ + (int)hf*75 + (c%75);
        w_sh[e] = wsrc[i*G_ + gcol];
    }
    if (t < 225){
        int gcol = (t/75)*H_ + (int)hf*75 + (t%75);
        bhh_sh[t] = net_bhh[k*G_ + gcol];
    }
    // h0 (full, both CTAs): [j][bb]
    for (int e = t; e < H_*32; e += 512){
        int j = e >> 5, bb = e & 31;
        sm7[GRN_H0 + e] = g_z[bb*H_ + j];
    }
    cluster_sync();

    const float* gxk = g_gxnet + (long long)k*2048*G_;
    int cur = 0;

    for (int s = 0; s < 64; s++){
        float* h_cur = sm7 + (cur ? GRN_H1 : GRN_H0);
        float* h_nxt = sm7 + (cur ? GRN_H0 : GRN_H1);

        if (t < 450){
            int col = t >> 1, pg = t & 1;   // pg: batch pair-group (16 batches each)
            unsigned long long acc[8];
            #pragma unroll
            for (int p = 0; p < 8; p++) acc[p] = 0ull;
            const float* wc = w_sh + col;
            const float* hb = h_cur + pg*16;
            #pragma unroll 2
            for (int i = 0; i < H_; i++){
                float w = wc[i*225];
                unsigned long long w2 = pk2(w, w);
                const ulonglong2* hp = (const ulonglong2*)(hb + i*32);
                ulonglong2 q0 = hp[0], q1 = hp[1], q2 = hp[2], q3 = hp[3];
                fma2(acc[0], w2, q0.x); fma2(acc[1], w2, q0.y);
                fma2(acc[2], w2, q1.x); fma2(acc[3], w2, q1.y);
                fma2(acc[4], w2, q2.x); fma2(acc[5], w2, q2.y);
                fma2(acc[6], w2, q3.x); fma2(acc[7], w2, q3.y);
            }
            float bh = bhh_sh[col];
            #pragma unroll
            for (int p = 0; p < 8; p++){
                float2 v = up2(acc[p]);
                gh_sh[(pg*16 + 2*p    )*226 + col] = v.x + bh;
                gh_sh[(pg*16 + 2*p + 1)*226 + col] = v.y + bh;
            }
        }
        __syncthreads();

        // update this CTA's 75 h-rows for all 32 batches; push to peer
        #pragma unroll
        for (int u = 0; u < 5; u++){
            int e = t + u*512;
            if (e < 2400){
                int bb = e / 75, jj = e - bb*75;
                const float* gx = gxk + (bb*K_ + s)*G_ + (int)hf*75 + jj;
                float ghr = gh_sh[bb*226 + jj];
                float ghz = gh_sh[bb*226 + 75  + jj];
                float ghn = gh_sh[bb*226 + 150 + jj];
                float r  = sigf(gx[0]     + ghr);
                float zz = sigf(gx[H_]    + ghz);
                float n  = tanhf_(gx[2*H_] + r*ghn);
                int j = (int)hf*75 + jj;
                float hnew = (1.f - zz)*n + zz*h_cur[j*32 + bb];
                h_nxt[j*32 + bb] = hnew;
                st_peer_f32(&h_nxt[j*32 + bb], peer, hnew);
            }
        }
        cluster_sync();
        cur ^= 1;
    }

    float* hfin = sm7 + (cur ? GRN_H1 : GRN_H0);
    #pragma unroll
    for (int u = 0; u < 5; u++){
        int e = t + u*512;
        if (e < 2400){
            int bb = e / 75, jj = e - bb*75;
            int j = (int)hf*75 + jj;
            out[bb*(K_*H_) + k*H_ + j] = hfin[j*32 + bb];
        }
    }
}

// ---------------- launch ----------------
extern "C" void kernel_launch(void* const* d_in, const int* in_sizes, int n_in,
                              void* d_out, int out_size)
{
    const float* x       = (const float*)d_in[0];
    const float* y       = (const float*)d_in[1];
    const float* z_noise = (const float*)d_in[2];
    const float* lin_w   = (const float*)d_in[3];
    const float* lin_b   = (const float*)d_in[4];
    const float* a       = (const float*)d_in[5];
    const float* bias    = (const float*)d_in[6];
    const float* gl_wih  = (const float*)d_in[7];
    const float* gl_whh  = (const float*)d_in[8];
    const float* gl_bih  = (const float*)d_in[9];
    const float* gl_bhh  = (const float*)d_in[10];
    const float* mu_w    = (const float*)d_in[11];
    const float* mu_b    = (const float*)d_in[12];
    const float* std_w   = (const float*)d_in[13];
    const float* std_b   = (const float*)d_in[14];
    const float* net_wih = (const float*)d_in[15];
    const float* net_whh = (const float*)d_in[16];
    const float* net_bih = (const float*)d_in[17];
    const float* net_bhh = (const float*)d_in[18];
    float* out = (float*)d_out;

    cudaFuncSetAttribute(k_gxnet,   cudaFuncAttributeMaxDynamicSharedMemorySize,
                         GXN_SMEM_FLOATS*4);
    cudaFuncSetAttribute(k_gru_net, cudaFuncAttributeMaxDynamicSharedMemorySize,
                         GRN_SMEM_FLOATS*4);

    k_prep<<<1024, 256>>>(lin_w, gl_wih, gl_whh, mu_w, std_w, net_wih, net_whh);
    k_wx<<<B_*K_, 128>>>(x, lin_b);
    k_gxnet<<<K_*2, 512, GXN_SMEM_FLOATS*4>>>(net_bih);
    k_attn<<<B_*K_, 256>>>(y, a, bias);
    k_gxg<<<K_*B_, 512>>>(gl_bih);
    k_gru_gl<<<B_, 512>>>(gl_bhh);
    k_z<<<B_, 160>>>(mu_b, std_b, z_noise);
    k_gru_net<<<K_*2, 512, GRN_SMEM_FLOATS*4>>>(net_bhh, out);
}

// round 4
// speedup vs baseline: 1.3298x; 1.1625x over previous
#include <cuda_runtime.h>

#define B_ 32
#define K_ 64
#define W_ 100
#define H_ 150
#define G_ 450
#define KW_ 6400
#define ALPHA_ 0.2f
#define THRES_ 0.0002f

// ---------------- scratch ----------------
__device__ float g_Wx[B_*K_*W_];
__device__ float g_cx[B_*K_*W_];
__device__ float g_linT[W_*W_];
__device__ float g_glwihT[W_*G_];
__device__ float2 g_glwhhP[(H_/2)*G_];           // [(i/2)][g] = (w_i, w_{i+1})
__device__ float g_muT[H_*H_];
__device__ float g_stdT[H_*H_];
__device__ float g_gxg[K_*B_*G_];                // (s*32+b)*450+g
__device__ float g_hl[B_*H_];
__device__ float g_z[B_*H_];
__device__ float g_gxnet[K_*B_*K_*G_];           // (k*2048 + b*64 + s)*450 + g

// ---------------- helpers ----------------
__device__ __forceinline__ unsigned long long pk2(float a, float b){
    unsigned long long r;
    asm("mov.b64 %0, {%1,%2};" : "=l"(r) : "f"(a), "f"(b));
    return r;
}
__device__ __forceinline__ void fma2(unsigned long long &d, unsigned long long a, unsigned long long b){
    asm("fma.rn.f32x2 %0, %1, %2, %0;" : "+l"(d) : "l"(a), "l"(b));
}
__device__ __forceinline__ float2 up2(unsigned long long v){
    float a, b;
    asm("mov.b64 {%0,%1}, %2;" : "=f"(a), "=f"(b) : "l"(v));
    float2 r; r.x = a; r.y = b; return r;
}
__device__ __forceinline__ float sigf(float x){ return __fdividef(1.f, 1.f + __expf(-x)); }
__device__ __forceinline__ float tanhf_(float x){
    float e = __expf(2.f * x);
    return 1.f - __fdividef(2.f, e + 1.f);
}
__device__ __forceinline__ unsigned cta_rank(){
    unsigned r; asm("mov.u32 %0, %%cluster_ctarank;" : "=r"(r)); return r;
}
__device__ __forceinline__ void cluster_sync(){
    asm volatile("barrier.cluster.arrive.aligned;" ::: "memory");
    asm volatile("barrier.cluster.wait.aligned;"  ::: "memory");
}
__device__ __forceinline__ void st_peer_f32(float* local_ptr, unsigned peer, float v){
    unsigned la = (unsigned)__cvta_generic_to_shared(local_ptr);
    unsigned ra;
    asm volatile("mapa.shared::cluster.u32 %0, %1, %2;" : "=r"(ra) : "r"(la), "r"(peer));
    asm volatile("st.shared::cluster.f32 [%0], %1;" :: "r"(ra), "f"(v) : "memory");
}
__device__ __forceinline__ void st_peer_f64(float* local_ptr, unsigned peer, unsigned long long v){
    unsigned la = (unsigned)__cvta_generic_to_shared(local_ptr);
    unsigned ra;
    asm volatile("mapa.shared::cluster.u32 %0, %1, %2;" : "=r"(ra) : "r"(la), "r"(peer));
    asm volatile("st.shared::cluster.b64 [%0], %1;" :: "r"(ra), "l"(v) : "memory");
}

// ---------------- prep (small matrices only) ----------------
__global__ void k_prep(const float* lin_w, const float* gl_wih, const float* gl_whh,
                       const float* mu_w, const float* std_w)
{
    int tid = blockIdx.x * blockDim.x + threadIdx.x;
    int stride = gridDim.x * blockDim.x;
    for (int e = tid; e < W_*W_; e += stride){
        int w = e / W_, i = e % W_;
        g_linT[i*W_ + w] = lin_w[e];
    }
    for (int e = tid; e < G_*W_; e += stride){
        int g = e / W_, i = e % W_;
        g_glwihT[i*G_ + g] = gl_wih[e];
    }
    for (int e = tid; e < (H_/2)*G_; e += stride){
        int i2 = e / G_, g = e % G_;
        float2 v;
        v.x = gl_whh[g*H_ + 2*i2];
        v.y = gl_whh[g*H_ + 2*i2 + 1];
        g_glwhhP[e] = v;
    }
    for (int e = tid; e < H_*H_; e += stride){
        int o = e / H_, i = e % H_;
        g_muT[i*H_ + o]  = mu_w[e];
        g_stdT[i*H_ + o] = std_w[e];
    }
}

// ---------------- K1: Wx ----------------
__global__ void k_wx(const float* __restrict__ x, const float* __restrict__ lin_b)
{
    __shared__ float xs[W_];
    int row = blockIdx.x;
    int t = threadIdx.x;
    if (t < W_) xs[t] = x[row*W_ + t];
    __syncthreads();
    if (t < W_){
        float acc = lin_b[t];
        #pragma unroll 4
        for (int i = 0; i < W_; i++) acc += xs[i] * g_linT[i*W_ + t];
        g_Wx[row*W_ + t] = acc;
    }
}

// ---------------- K2: attention (single data pass) ----------------
__global__ __launch_bounds__(256) void k_attn(const float* __restrict__ y,
                       const float* __restrict__ a, const float* __restrict__ bias)
{
    int b = blockIdx.x >> 6;
    int k = blockIdx.x & 63;
    const float a0 = a[0], a1 = a[1];
    const float yb = a0 * y[b*K_ + k];
    const float* vrow = g_Wx + b*KW_;
    const float* brow = bias + k*KW_;
    int t = threadIdx.x;             // 256

    __shared__ float red[256];

    float e_loc[25], v_loc[25];
    float m = -3.4e38f;
    #pragma unroll
    for (int jj = 0; jj < 25; jj++){
        int j = t + jj*256;
        float v = vrow[j];
        float e = yb + a1*v + brow[j];
        e = e > 0.f ? e : ALPHA_*e;
        e_loc[jj] = e; v_loc[jj] = v;
        m = fmaxf(m, e);
    }
    red[t] = m; __syncthreads();
    for (int o = 128; o > 0; o >>= 1){
        if (t < o) red[t] = fmaxf(red[t], red[t+o]);
        __syncthreads();
    }
    float M = red[0]; __syncthreads();

    float ssum = 0.f;
    #pragma unroll
    for (int jj = 0; jj < 25; jj++) ssum += __expf(e_loc[jj] - M);
    red[t] = ssum; __syncthreads();
    for (int o = 128; o > 0; o >>= 1){
        if (t < o) red[t] += red[t+o];
        __syncthreads();
    }
    float S = red[0]; __syncthreads();

    float T = M + __logf(THRES_ * S);

    float acc = 0.f;
    #pragma unroll
    for (int jj = 0; jj < 25; jj++) if (e_loc[jj] >= T) acc += v_loc[jj];
    red[t] = acc; __syncthreads();
    for (int o = 128; o > 0; o >>= 1){
        if (t < o) red[t] += red[t+o];
        __syncthreads();
    }
    float sbk = red[0];

    if (t < W_){
        int row = b*K_ + k;
        g_cx[row*W_ + t] = g_Wx[row*W_ + t] + sbk;
    }
}

// ---------------- K3: gx for global GRU ----------------
__global__ void k_gxg(const float* __restrict__ gl_bih)
{
    int s = blockIdx.x >> 5;
    int b = blockIdx.x & 31;
    __shared__ float cx[W_];
    int t = threadIdx.x;             // 512
    if (t < W_) cx[t] = g_cx[(b*K_ + s)*W_ + t];
    __syncthreads();
    if (t < G_){
        float acc = gl_bih[t];
        #pragma unroll 4
        for (int i = 0; i < W_; i++) acc += cx[i] * g_glwihT[i*G_ + t];
        g_gxg[(s*B_ + b)*G_ + t] = acc;
    }
}

// ---------------- K4: global GRU — cluster(2) gate split, weights in smem ------
// grid 64, cluster 2: b = bid>>1, hf = rank. CTA owns gate-local cols
// [hf*75, hf*75+75) of each gate (225 cols), weights (i2-paired) 135KB in smem.
#define GL_W    0
#define GL_H0   33752
#define GL_H1   33912
#define GL_GH   34072
#define GL_BHH  34304
#define GL_SMEM_FLOATS (GL_BHH + 232)

__global__ __launch_bounds__(256, 1) __cluster_dims__(2,1,1)
void k_gru_gl(const float* __restrict__ gl_bhh)
{
    extern __shared__ __align__(16) float smg[];
    int b = blockIdx.x >> 1;
    unsigned hf = cta_rank();
    unsigned peer = hf ^ 1u;
    int t = threadIdx.x;             // 256

    float2* w2_sh  = (float2*)(smg + GL_W);   // [i2][225]
    float*  gh_sh  = smg + GL_GH;             // [225]
    float*  bhh_sh = smg + GL_BHH;

    // stage packed weights: w2_sh[i2*225 + c] = glwhhP[i2*450 + gcol]
    for (int e = t; e < 75*225; e += 256){
        int i2 = e / 225, c = e - i2*225;
        int gcol = (c/75)*H_ + (int)hf*75 + (c%75);
        w2_sh[e] = g_glwhhP[i2*G_ + gcol];
    }
    if (t < 225){
        int gcol = (t/75)*H_ + (int)hf*75 + (t%75);
        bhh_sh[t] = gl_bhh[gcol];
    }
    if (t < 152){ smg[GL_H0 + t] = 0.f; smg[GL_H1 + t] = 0.f; }
    cluster_sync();

    int cur = 0;
    for (int s = 0; s < 64; s++){
        float* h_cur = smg + (cur ? GL_H1 : GL_H0);
        float* h_nxt = smg + (cur ? GL_H0 : GL_H1);

        if (t < 225){
            unsigned long long acc = 0ull;
            const unsigned long long* hp = (const unsigned long long*)h_cur;
            const float2* wc = w2_sh + t;
            #pragma unroll 5
            for (int i2 = 0; i2 < 75; i2++){
                unsigned long long w2 = *(const unsigned long long*)(wc + i2*225);
                fma2(acc, w2, hp[i2]);
            }
            float2 v = up2(acc);
            gh_sh[t] = v.x + v.y + bhh_sh[t];
        }
        __syncthreads();

        if (t < 75){
            int j = (int)hf*75 + t;
            const float* gx = g_gxg + (s*B_ + b)*G_;
            float r  = sigf(gx[j]        + gh_sh[t]);
            float zz = sigf(gx[H_ + j]   + gh_sh[75 + t]);
            float n  = tanhf_(gx[2*H_+j] + r * gh_sh[150 + t]);
            float hnew = (1.f - zz)*n + zz*h_cur[j];
            h_nxt[j] = hnew;
            st_peer_f32(&h_nxt[j], peer, hnew);
        }
        cluster_sync();
        cur ^= 1;
    }
    float* hfin = smg + (cur ? GL_H1 : GL_H0);
    if (t < 75){
        int j = (int)hf*75 + t;
        g_hl[b*H_ + j] = hfin[j];
    }
}

// ---------------- K5: z ----------------
__global__ void k_z(const float* __restrict__ mu_b, const float* __restrict__ std_b,
                    const float* __restrict__ z_noise)
{
    int b = blockIdx.x, t = threadIdx.x;   // 160
    __shared__ float hs[152];
    if (t < H_) hs[t] = g_hl[b*H_ + t];
    __syncthreads();
    if (t < H_){
        float mu = mu_b[t], lv = std_b[t];
        #pragma unroll 2
        for (int i = 0; i < H_; i++){
            float h = hs[i];
            mu += h * g_muT[i*H_ + t];
            lv += h * g_stdT[i*H_ + t];
        }
        g_z[b*H_ + t] = mu + __expf(0.5f*lv) * z_noise[b*H_ + t];
    }
}

// ---------------- K6: gxnet GEMM, weights staged from original layout ----------
#define GXN_SMEM_FLOATS (45000 + 1600)
__global__ __launch_bounds__(512, 1) void k_gxnet(const float* __restrict__ net_wih,
                                                  const float* __restrict__ net_bih)
{
    extern __shared__ __align__(16) float sm6[];
    float* w_sh = sm6;               // [i][450]
    float* A_sh = sm6 + 45000;       // [i][16]
    int k    = blockIdx.x >> 1;
    int half = blockIdx.x & 1;
    int t = threadIdx.x;             // 512

    // stage transpose: read [g][i] coalesced, write [i][450+g] (2-way bank ok)
    const float* wsrc = net_wih + k*(G_*W_);
    for (int e = t; e < G_*W_; e += 512){
        int g = e / W_, i = e - g*W_;
        w_sh[i*G_ + g] = wsrc[e];
    }

    float bi = (t < G_) ? net_bih[k*G_ + t] : 0.f;

    int row_base = half*1024;
    for (int rb = 0; rb < 64; rb++){
        int r0 = row_base + rb*16;
        const float* Ab = g_Wx + r0*W_;
        float a0 = Ab[t];
        float a1 = Ab[t + 512];
        float a2 = Ab[t + 1024];
        float a3 = (t < 64) ? Ab[t + 1536] : 0.f;
        __syncthreads();
        {
            int e = t;          A_sh[(e%W_)*16 + e/W_] = a0;
            e = t + 512;        A_sh[(e%W_)*16 + e/W_] = a1;
            e = t + 1024;       A_sh[(e%W_)*16 + e/W_] = a2;
            if (t < 64){ e = t + 1536; A_sh[(e%W_)*16 + e/W_] = a3; }
        }
        __syncthreads();

        if (t < G_){
            unsigned long long acc[8];
            #pragma unroll
            for (int p = 0; p < 8; p++) acc[p] = 0ull;
            #pragma unroll 2
            for (int i = 0; i < W_; i++){
                float w = w_sh[i*G_ + t];
                unsigned long long w2 = pk2(w, w);
                const ulonglong2* hp = (const ulonglong2*)&A_sh[i*16];
                ulonglong2 q0 = hp[0], q1 = hp[1], q2 = hp[2], q3 = hp[3];
                fma2(acc[0], w2, q0.x); fma2(acc[1], w2, q0.y);
                fma2(acc[2], w2, q1.x); fma2(acc[3], w2, q1.y);
                fma2(acc[4], w2, q2.x); fma2(acc[5], w2, q2.y);
                fma2(acc[6], w2, q3.x); fma2(acc[7], w2, q3.y);
            }
            #pragma unroll
            for (int p = 0; p < 8; p++){
                float2 v = up2(acc[p]);
                g_gxnet[(k*2048 + r0 + 2*p    )*G_ + t] = v.x + bi;
                g_gxnet[(k*2048 + r0 + 2*p + 1)*G_ + t] = v.y + bi;
            }
        }
    }
}

// ---------------- K7: net GRUs — cluster(2) gate split, smem weights ------------
#define GRN_W   0
#define GRN_H0  33752
#define GRN_H1  (33752 + 4800)
#define GRN_GH  (33752 + 9600)
#define GRN_BHH (GRN_GH + 32*226)
#define GRN_SMEM_FLOATS (GRN_BHH + 232)

__global__ __launch_bounds__(512, 1) __cluster_dims__(2,1,1)
void k_gru_net(const float* __restrict__ net_whh, const float* __restrict__ net_bhh,
               float* __restrict__ out)
{
    extern __shared__ __align__(16) float sm7[];
    int k = blockIdx.x >> 1;
    unsigned hf = cta_rank();
    unsigned peer = hf ^ 1u;
    int t = threadIdx.x;             // 512

    float* w_sh   = sm7 + GRN_W;     // [i][225]
    float* gh_sh  = sm7 + GRN_GH;    // [bb][226]
    float* bhh_sh = sm7 + GRN_BHH;

    // stage from original net_whh [k][g][i]: coalesced reads, conflict-free writes
    const float* wsrc = net_whh + k*(G_*H_);
    for (int e = t; e < 225*H_; e += 512){
        int c = e / H_, i = e - c*H_;
        int gcol = (c/75)*H_ + (int)hf*75 + (c%75);
        w_sh[i*225 + c] = wsrc[gcol*H_ + i];
    }
    if (t < 225){
        int gcol = (t/75)*H_ + (int)hf*75 + (t%75);
        bhh_sh[t] = net_bhh[k*G_ + gcol];
    }
    for (int e = t; e < H_*32; e += 512){
        int j = e >> 5, bb = e & 31;
        sm7[GRN_H0 + e] = g_z[bb*H_ + j];
    }
    cluster_sync();

    const float* gxk = g_gxnet + (long long)k*2048*G_;
    int cur = 0;

    for (int s = 0; s < 64; s++){
        float* h_cur = sm7 + (cur ? GRN_H1 : GRN_H0);
        float* h_nxt = sm7 + (cur ? GRN_H0 : GRN_H1);

        if (t < 450){
            int col = t >> 1, pg = t & 1;
            unsigned long long acc[8];
            #pragma unroll
            for (int p = 0; p < 8; p++) acc[p] = 0ull;
            const float* wc = w_sh + col;
            const float* hb = h_cur + pg*16;
            #pragma unroll 2
            for (int i = 0; i < H_; i++){
                float w = wc[i*225];
                unsigned long long w2 = pk2(w, w);
                const ulonglong2* hp = (const ulonglong2*)(hb + i*32);
                ulonglong2 q0 = hp[0], q1 = hp[1], q2 = hp[2], q3 = hp[3];
                fma2(acc[0], w2, q0.x); fma2(acc[1], w2, q0.y);
                fma2(acc[2], w2, q1.x); fma2(acc[3], w2, q1.y);
                fma2(acc[4], w2, q2.x); fma2(acc[5], w2, q2.y);
                fma2(acc[6], w2, q3.x); fma2(acc[7], w2, q3.y);
            }
            float bh = bhh_sh[col];
            #pragma unroll
            for (int p = 0; p < 8; p++){
                float2 v = up2(acc[p]);
                gh_sh[(pg*16 + 2*p    )*226 + col] = v.x + bh;
                gh_sh[(pg*16 + 2*p + 1)*226 + col] = v.y + bh;
            }
        }
        __syncthreads();

        // update: thread handles (jj, batch pair bb0=2*bbp, bb0+1); b64 pushes
        #pragma unroll
        for (int u = 0; u < 3; u++){
            int e = t + u*512;
            if (e < 1200){
                int jj = e >> 4, bbp = e & 15;
                int bb0 = bbp*2;
                int j = (int)hf*75 + jj;
                const float* gx0 = gxk + (bb0*K_ + s)*G_ + j;
                const float* gx1 = gx0 + K_*G_;
                float ghr0 = gh_sh[bb0*226 + jj];
                float ghz0 = gh_sh[bb0*226 + 75  + jj];
                float ghn0 = gh_sh[bb0*226 + 150 + jj];
                float ghr1 = gh_sh[(bb0+1)*226 + jj];
                float ghz1 = gh_sh[(bb0+1)*226 + 75  + jj];
                float ghn1 = gh_sh[(bb0+1)*226 + 150 + jj];
                float r0  = sigf(gx0[0]     + ghr0);
                float zz0 = sigf(gx0[H_]    + ghz0);
                float n0  = tanhf_(gx0[2*H_] + r0*ghn0);
                float r1  = sigf(gx1[0]     + ghr1);
                float zz1 = sigf(gx1[H_]    + ghz1);
                float n1  = tanhf_(gx1[2*H_] + r1*ghn1);
                float h0o = h_cur[j*32 + bb0];
                float h1o = h_cur[j*32 + bb0 + 1];
                float hn0 = (1.f - zz0)*n0 + zz0*h0o;
                float hn1 = (1.f - zz1)*n1 + zz1*h1o;
                unsigned long long pv = pk2(hn0, hn1);
                *(unsigned long long*)&h_nxt[j*32 + bb0] = pv;
                st_peer_f64(&h_nxt[j*32 + bb0], peer, pv);
            }
        }
        cluster_sync();
        cur ^= 1;
    }

    float* hfin = sm7 + (cur ? GRN_H1 : GRN_H0);
    #pragma unroll
    for (int u = 0; u < 5; u++){
        int e = t + u*512;
        if (e < 2400){
            int bb = e / 75, jj = e - bb*75;
            int j = (int)hf*75 + jj;
            out[bb*(K_*H_) + k*H_ + j] = hfin[j*32 + bb];
        }
    }
}

// ---------------- launch ----------------
extern "C" void kernel_launch(void* const* d_in, const int* in_sizes, int n_in,
                              void* d_out, int out_size)
{
    const float* x       = (const float*)d_in[0];
    const float* y       = (const float*)d_in[1];
    const float* z_noise = (const float*)d_in[2];
    const float* lin_w   = (const float*)d_in[3];
    const float* lin_b   = (const float*)d_in[4];
    const float* a       = (const float*)d_in[5];
    const float* bias    = (const float*)d_in[6];
    const float* gl_wih  = (const float*)d_in[7];
    const float* gl_whh  = (const float*)d_in[8];
    const float* gl_bih  = (const float*)d_in[9];
    const float* gl_bhh  = (const float*)d_in[10];
    const float* mu_w    = (const float*)d_in[11];
    const float* mu_b    = (const float*)d_in[12];
    const float* std_w   = (const float*)d_in[13];
    const float* std_b   = (const float*)d_in[14];
    const float* net_wih = (const float*)d_in[15];
    const float* net_whh = (const float*)d_in[16];
    const float* net_bih = (const float*)d_in[17];
    const float* net_bhh = (const float*)d_in[18];
    float* out = (float*)d_out;

    static cudaStream_t s_side = nullptr;
    static cudaEvent_t ev1 = nullptr, ev2 = nullptr;
    if (!s_side){
        cudaStreamCreateWithFlags(&s_side, cudaStreamNonBlocking);
        cudaEventCreateWithFlags(&ev1, cudaEventDisableTiming);
        cudaEventCreateWithFlags(&ev2, cudaEventDisableTiming);
        cudaFuncSetAttribute(k_gxnet,   cudaFuncAttributeMaxDynamicSharedMemorySize,
                             GXN_SMEM_FLOATS*4);
        cudaFuncSetAttribute(k_gru_net, cudaFuncAttributeMaxDynamicSharedMemorySize,
                             GRN_SMEM_FLOATS*4);
        cudaFuncSetAttribute(k_gru_gl,  cudaFuncAttributeMaxDynamicSharedMemorySize,
                             GL_SMEM_FLOATS*4);
    }

    k_prep<<<256, 256>>>(lin_w, gl_wih, gl_whh, mu_w, std_w);
    k_wx<<<B_*K_, 128>>>(x, lin_b);

    // fork side chain: attn -> gxg -> gru_gl -> z  (hidden under k_gxnet)
    cudaEventRecord(ev1, 0);
    cudaStreamWaitEvent(s_side, ev1, 0);
    k_attn<<<B_*K_, 256, 0, s_side>>>(y, a, bias);
    k_gxg<<<K_*B_, 512, 0, s_side>>>(gl_bih);
    k_gru_gl<<<B_*2, 256, GL_SMEM_FLOATS*4, s_side>>>(gl_bhh);
    k_z<<<B_, 160, 0, s_side>>>(mu_b, std_b, z_noise);
    cudaEventRecord(ev2, s_side);

    k_gxnet<<<K_*2, 512, GXN_SMEM_FLOATS*4>>>(net_wih, net_bih);

    cudaStreamWaitEvent(0, ev2, 0);
    k_gru_net<<<K_*2, 512, GRN_SMEM_FLOATS*4>>>(net_whh, net_bhh, out);
}

// round 5
// speedup vs baseline: 1.8030x; 1.3558x over previous
#include <cuda_runtime.h>
#include <cuda_fp16.h>

#define B_ 32
#define K_ 64
#define W_ 100
#define H_ 150
#define G_ 450
#define KW_ 6400
#define ALPHA_ 0.2f
#define THRES_ 0.0002f

// ---------------- scratch ----------------
__device__ float g_Wx[B_*K_*W_];
__device__ float g_cx[B_*K_*W_];
__device__ float g_linT[W_*W_];
__device__ float g_glwihT[W_*G_];
__device__ float2 g_glwhhP[(H_/2)*G_];
__device__ float g_muT[H_*H_];
__device__ float g_stdT[H_*H_];
__device__ float g_gxg[K_*B_*G_];
__device__ float g_hl[B_*H_];
__device__ float g_z[B_*H_];
__device__ __half g_gxnet_h[K_*B_*K_*G_];        // [k][s][b][g]  (118MB, L2-resident)

// ---------------- helpers ----------------
__device__ __forceinline__ unsigned long long pk2(float a, float b){
    unsigned long long r;
    asm("mov.b64 %0, {%1,%2};" : "=l"(r) : "f"(a), "f"(b));
    return r;
}
__device__ __forceinline__ void fma2(unsigned long long &d, unsigned long long a, unsigned long long b){
    asm("fma.rn.f32x2 %0, %1, %2, %0;" : "+l"(d) : "l"(a), "l"(b));
}
__device__ __forceinline__ float2 up2(unsigned long long v){
    float a, b;
    asm("mov.b64 {%0,%1}, %2;" : "=f"(a), "=f"(b) : "l"(v));
    float2 r; r.x = a; r.y = b; return r;
}
__device__ __forceinline__ float sigf(float x){ return __fdividef(1.f, 1.f + __expf(-x)); }
__device__ __forceinline__ float tanhf_(float x){
    float e = __expf(2.f * x);
    return 1.f - __fdividef(2.f, e + 1.f);
}
__device__ __forceinline__ unsigned cta_rank(){
    unsigned r; asm("mov.u32 %0, %%cluster_ctarank;" : "=r"(r)); return r;
}
__device__ __forceinline__ void cluster_sync(){
    asm volatile("barrier.cluster.arrive.aligned;" ::: "memory");
    asm volatile("barrier.cluster.wait.aligned;"  ::: "memory");
}
__device__ __forceinline__ void st_peer_f32(float* local_ptr, unsigned peer, float v){
    unsigned la = (unsigned)__cvta_generic_to_shared(local_ptr);
    unsigned ra;
    asm volatile("mapa.shared::cluster.u32 %0, %1, %2;" : "=r"(ra) : "r"(la), "r"(peer));
    asm volatile("st.shared::cluster.f32 [%0], %1;" :: "r"(ra), "f"(v) : "memory");
}
__device__ __forceinline__ void st_peer_f64(float* local_ptr, unsigned peer, unsigned long long v){
    unsigned la = (unsigned)__cvta_generic_to_shared(local_ptr);
    unsigned ra;
    asm volatile("mapa.shared::cluster.u32 %0, %1, %2;" : "=r"(ra) : "r"(la), "r"(peer));
    asm volatile("st.shared::cluster.b64 [%0], %1;" :: "r"(ra), "l"(v) : "memory");
}

// ---------------- prep ----------------
__global__ void k_prep(const float* lin_w, const float* gl_wih, const float* gl_whh,
                       const float* mu_w, const float* std_w)
{
    int tid = blockIdx.x * blockDim.x + threadIdx.x;
    int stride = gridDim.x * blockDim.x;
    for (int e = tid; e < W_*W_; e += stride){
        int w = e / W_, i = e % W_;
        g_linT[i*W_ + w] = lin_w[e];
    }
    for (int e = tid; e < G_*W_; e += stride){
        int g = e / W_, i = e % W_;
        g_glwihT[i*G_ + g] = gl_wih[e];
    }
    for (int e = tid; e < (H_/2)*G_; e += stride){
        int i2 = e / G_, g = e % G_;
        float2 v;
        v.x = gl_whh[g*H_ + 2*i2];
        v.y = gl_whh[g*H_ + 2*i2 + 1];
        g_glwhhP[e] = v;
    }
    for (int e = tid; e < H_*H_; e += stride){
        int o = e / H_, i = e % H_;
        g_muT[i*H_ + o]  = mu_w[e];
        g_stdT[i*H_ + o] = std_w[e];
    }
}

// ---------------- K1: Wx ----------------
__global__ void k_wx(const float* __restrict__ x, const float* __restrict__ lin_b)
{
    __shared__ float xs[W_];
    int row = blockIdx.x;
    int t = threadIdx.x;
    if (t < W_) xs[t] = x[row*W_ + t];
    __syncthreads();
    if (t < W_){
        float acc = lin_b[t];
        #pragma unroll 4
        for (int i = 0; i < W_; i++) acc += xs[i] * g_linT[i*W_ + t];
        g_Wx[row*W_ + t] = acc;
    }
}

// ---------------- K2: attention ----------------
__global__ __launch_bounds__(256) void k_attn(const float* __restrict__ y,
                       const float* __restrict__ a, const float* __restrict__ bias)
{
    int b = blockIdx.x >> 6;
    int k = blockIdx.x & 63;
    const float a0 = a[0], a1 = a[1];
    const float yb = a0 * y[b*K_ + k];
    const float* vrow = g_Wx + b*KW_;
    const float* brow = bias + k*KW_;
    int t = threadIdx.x;             // 256

    __shared__ float red[256];

    float e_loc[25], v_loc[25];
    float m = -3.4e38f;
    #pragma unroll
    for (int jj = 0; jj < 25; jj++){
        int j = t + jj*256;
        float v = vrow[j];
        float e = yb + a1*v + brow[j];
        e = e > 0.f ? e : ALPHA_*e;
        e_loc[jj] = e; v_loc[jj] = v;
        m = fmaxf(m, e);
    }
    red[t] = m; __syncthreads();
    for (int o = 128; o > 0; o >>= 1){
        if (t < o) red[t] = fmaxf(red[t], red[t+o]);
        __syncthreads();
    }
    float M = red[0]; __syncthreads();

    float ssum = 0.f;
    #pragma unroll
    for (int jj = 0; jj < 25; jj++) ssum += __expf(e_loc[jj] - M);
    red[t] = ssum; __syncthreads();
    for (int o = 128; o > 0; o >>= 1){
        if (t < o) red[t] += red[t+o];
        __syncthreads();
    }
    float S = red[0]; __syncthreads();

    float T = M + __logf(THRES_ * S);

    float acc = 0.f;
    #pragma unroll
    for (int jj = 0; jj < 25; jj++) if (e_loc[jj] >= T) acc += v_loc[jj];
    red[t] = acc; __syncthreads();
    for (int o = 128; o > 0; o >>= 1){
        if (t < o) red[t] += red[t+o];
        __syncthreads();
    }
    float sbk = red[0];

    if (t < W_){
        int row = b*K_ + k;
        g_cx[row*W_ + t] = g_Wx[row*W_ + t] + sbk;
    }
}

// ---------------- K3: gx for global GRU ----------------
__global__ void k_gxg(const float* __restrict__ gl_bih)
{
    int s = blockIdx.x >> 5;
    int b = blockIdx.x & 31;
    __shared__ float cx[W_];
    int t = threadIdx.x;             // 512
    if (t < W_) cx[t] = g_cx[(b*K_ + s)*W_ + t];
    __syncthreads();
    if (t < G_){
        float acc = gl_bih[t];
        #pragma unroll 4
        for (int i = 0; i < W_; i++) acc += cx[i] * g_glwihT[i*G_ + t];
        g_gxg[(s*B_ + b)*G_ + t] = acc;
    }
}

// ---------------- K4: global GRU (cluster 2, smem weights) ----------------
#define GL_W    0
#define GL_H0   33752
#define GL_H1   33912
#define GL_GH   34072
#define GL_BHH  34304
#define GL_SMEM_FLOATS (GL_BHH + 232)

__global__ __launch_bounds__(256, 1) __cluster_dims__(2,1,1)
void k_gru_gl(const float* __restrict__ gl_bhh)
{
    extern __shared__ __align__(16) float smg[];
    int b = blockIdx.x >> 1;
    unsigned hf = cta_rank();
    unsigned peer = hf ^ 1u;
    int t = threadIdx.x;             // 256

    float2* w2_sh  = (float2*)(smg + GL_W);
    float*  gh_sh  = smg + GL_GH;
    float*  bhh_sh = smg + GL_BHH;

    for (int e = t; e < 75*225; e += 256){
        int i2 = e / 225, c = e - i2*225;
        int gcol = (c/75)*H_ + (int)hf*75 + (c%75);
        w2_sh[e] = g_glwhhP[i2*G_ + gcol];
    }
    if (t < 225){
        int gcol = (t/75)*H_ + (int)hf*75 + (t%75);
        bhh_sh[t] = gl_bhh[gcol];
    }
    if (t < 152){ smg[GL_H0 + t] = 0.f; smg[GL_H1 + t] = 0.f; }
    cluster_sync();

    int cur = 0;
    for (int s = 0; s < 64; s++){
        float* h_cur = smg + (cur ? GL_H1 : GL_H0);
        float* h_nxt = smg + (cur ? GL_H0 : GL_H1);

        if (t < 225){
            unsigned long long acc = 0ull;
            const unsigned long long* hp = (const unsigned long long*)h_cur;
            const float2* wc = w2_sh + t;
            #pragma unroll 5
            for (int i2 = 0; i2 < 75; i2++){
                unsigned long long w2 = *(const unsigned long long*)(wc + i2*225);
                fma2(acc, w2, hp[i2]);
            }
            float2 v = up2(acc);
            gh_sh[t] = v.x + v.y + bhh_sh[t];
        }
        __syncthreads();

        if (t < 75){
            int j = (int)hf*75 + t;
            const float* gx = g_gxg + (s*B_ + b)*G_;
            float r  = sigf(gx[j]        + gh_sh[t]);
            float zz = sigf(gx[H_ + j]   + gh_sh[75 + t]);
            float n  = tanhf_(gx[2*H_+j] + r * gh_sh[150 + t]);
            float hnew = (1.f - zz)*n + zz*h_cur[j];
            h_nxt[j] = hnew;
            st_peer_f32(&h_nxt[j], peer, hnew);
        }
        cluster_sync();
        cur ^= 1;
    }
    float* hfin = smg + (cur ? GL_H1 : GL_H0);
    if (t < 75){
        int j = (int)hf*75 + t;
        g_hl[b*H_ + j] = hfin[j];
    }
}

// ---------------- K5: z ----------------
__global__ void k_z(const float* __restrict__ mu_b, const float* __restrict__ std_b,
                    const float* __restrict__ z_noise)
{
    int b = blockIdx.x, t = threadIdx.x;   // 160
    __shared__ float hs[152];
    if (t < H_) hs[t] = g_hl[b*H_ + t];
    __syncthreads();
    if (t < H_){
        float mu = mu_b[t], lv = std_b[t];
        #pragma unroll 2
        for (int i = 0; i < H_; i++){
            float h = hs[i];
            mu += h * g_muT[i*H_ + t];
            lv += h * g_stdT[i*H_ + t];
        }
        g_z[b*H_ + t] = mu + __expf(0.5f*lv) * z_noise[b*H_ + t];
    }
}

// ---------------- K6: gxnet GEMM — TC=2 blocking, double-buffered A, fp16 out ----
// 128 CTAs: k = bid>>1, half = bid&1 (1024 rows). 64 blocks of 16 rows.
// w_sh [i][452] padded (cols 450,451 zero). A [i][16] double buffered.
#define GXN_W    0
#define GXN_A0   45200
#define GXN_A1   (45200 + 1600)
#define GXN_SMEM_FLOATS (45200 + 3200)

__global__ __launch_bounds__(512, 1) void k_gxnet(const float* __restrict__ net_wih,
                                                  const float* __restrict__ net_bih)
{
    extern __shared__ __align__(16) float sm6[];
    float* w_sh = sm6 + GXN_W;       // [i][452]
    int k    = blockIdx.x >> 1;
    int half = blockIdx.x & 1;
    int t = threadIdx.x;             // 512

    const float* wsrc = net_wih + k*(G_*W_);
    for (int e = t; e < G_*W_; e += 512){
        int g = e / W_, i = e - g*W_;
        w_sh[i*452 + g] = wsrc[e];
    }
    for (int e = t; e < 2*W_; e += 512){
        int i = e >> 1;
        w_sh[i*452 + 450 + (e & 1)] = 0.f;
    }

    int c0 = 2*t, c1 = 2*t + 1;      // cols for t<226
    float bi0 = (c0 < G_) ? net_bih[k*G_ + c0] : 0.f;
    float bi1 = (c1 < G_) ? net_bih[k*G_ + c1] : 0.f;

    int row_base = half*1024;
    float* Ab0 = sm6 + GXN_A0;
    float* Ab1 = sm6 + GXN_A1;

    // stage block 0 (pairs, STS.64, conflict-lite)
    {
        const float* Ab = g_Wx + row_base*W_;
        for (int e = t; e < 800; e += 512){
            int i = e % W_, rp = e / W_;
            float2 v; v.x = Ab[(2*rp)*W_ + i]; v.y = Ab[(2*rp+1)*W_ + i];
            *(float2*)&Ab0[i*16 + 2*rp] = v;
        }
    }
    __syncthreads();

    for (int rb = 0; rb < 64; rb++){
        float* A_cur = (rb & 1) ? Ab1 : Ab0;
        float* A_nxt = (rb & 1) ? Ab0 : Ab1;
        int r0 = row_base + rb*16;

        // prefetch next block into regs (issue early)
        float2 pf0, pf1; pf1.x = 0.f; pf1.y = 0.f;
        if (rb < 63){
            const float* Ab = g_Wx + (r0 + 16)*W_;
            { int i = t % W_, rp = t / W_;
              pf0.x = Ab[(2*rp)*W_ + i]; pf0.y = Ab[(2*rp+1)*W_ + i]; }
            if (t < 288){ int e = t + 512; int i = e % W_, rp = e / W_;
              pf1.x = Ab[(2*rp)*W_ + i]; pf1.y = Ab[(2*rp+1)*W_ + i]; }
        }

        if (t < 226){
            unsigned long long acc[16];
            #pragma unroll
            for (int p = 0; p < 16; p++) acc[p] = 0ull;
            const float2* wp2 = (const float2*)w_sh + t;   // pair (c0,c1) at i*226 float2s
            #pragma unroll 2
            for (int i = 0; i < W_; i++){
                float2 w = wp2[i*226];
                unsigned long long w20 = pk2(w.x, w.x);
                unsigned long long w21 = pk2(w.y, w.y);
                const ulonglong2* hp = (const ulonglong2*)&A_cur[i*16];
                ulonglong2 q0 = hp[0], q1 = hp[1], q2 = hp[2], q3 = hp[3];
                fma2(acc[0],  w20, q0.x); fma2(acc[1],  w20, q0.y);
                fma2(acc[2],  w20, q1.x); fma2(acc[3],  w20, q1.y);
                fma2(acc[4],  w20, q2.x); fma2(acc[5],  w20, q2.y);
                fma2(acc[6],  w20, q3.x); fma2(acc[7],  w20, q3.y);
                fma2(acc[8],  w21, q0.x); fma2(acc[9],  w21, q0.y);
                fma2(acc[10], w21, q1.x); fma2(acc[11], w21, q1.y);
                fma2(acc[12], w21, q2.x); fma2(acc[13], w21, q2.y);
                fma2(acc[14], w21, q3.x); fma2(acc[15], w21, q3.y);
            }
            // store: row r = r0+2p (+1); layout [k][s][b][g], r = b*64+s
            #pragma unroll
            for (int p = 0; p < 8; p++){
                int ra = r0 + 2*p, rbw = ra + 1;
                long long ia = (long long)(k*2048 + (ra & 63)*B_ + (ra >> 6))*G_;
                long long ib = (long long)(k*2048 + (rbw & 63)*B_ + (rbw >> 6))*G_;
                float2 v0 = up2(acc[p]);
                float2 v1 = up2(acc[8 + p]);
                if (c0 < G_){
                    g_gxnet_h[ia + c0] = __float2half(v0.x + bi0);
                    g_gxnet_h[ib + c0] = __float2half(v0.y + bi0);
                }
                if (c1 < G_){
                    g_gxnet_h[ia + c1] = __float2half(v1.x + bi1);
                    g_gxnet_h[ib + c1] = __float2half(v1.y + bi1);
                }
            }
        }

        // write prefetched next block (overlaps other warps' compute)
        if (rb < 63){
            { int i = t % W_, rp = t / W_; *(float2*)&A_nxt[i*16 + 2*rp] = pf0; }
            if (t < 288){ int e = t + 512; int i = e % W_, rp = e / W_;
                          *(float2*)&A_nxt[i*16 + 2*rp] = pf1; }
        }
        __syncthreads();
    }
}

// ---------------- K7: net GRUs — cluster(2), TC=2 blocking, fp16 gx ------------
// w_sh [i][226] (col 225 zero pad). gh_sh [bb][228]. h [j][32] double buffered.
#define GRN_W    0
#define GRN_H0   33904
#define GRN_H1   (33904 + 4800)
#define GRN_GH   (33904 + 9600)
#define GRN_BHH  (GRN_GH + 32*228)
#define GRN_SMEM_FLOATS (GRN_BHH + 232)

__global__ __launch_bounds__(512, 1) __cluster_dims__(2,1,1)
void k_gru_net(const float* __restrict__ net_whh, const float* __restrict__ net_bhh,
               float* __restrict__ out)
{
    extern __shared__ __align__(16) float sm7[];
    int k = blockIdx.x >> 1;
    unsigned hf = cta_rank();
    unsigned peer = hf ^ 1u;
    int t = threadIdx.x;             // 512

    float* w_sh   = sm7 + GRN_W;     // [i][226]
    float* gh_sh  = sm7 + GRN_GH;    // [bb][228]
    float* bhh_sh = sm7 + GRN_BHH;

    // stage weights from original [k][g][i] (coalesced reads)
    const float* wsrc = net_whh + k*(G_*H_);
    for (int e = t; e < 225*H_; e += 512){
        int c = e / H_, i = e - c*H_;
        int gcol = (c/75)*H_ + (int)hf*75 + (c%75);
        w_sh[i*226 + c] = wsrc[gcol*H_ + i];
    }
    for (int e = t; e < H_; e += 512) w_sh[e*226 + 225] = 0.f;
    if (t < 225){
        int gcol = (t/75)*H_ + (int)hf*75 + (t%75);
        bhh_sh[t] = net_bhh[k*G_ + gcol];
    }
    if (t == 225 || t == 226) bhh_sh[225] = 0.f;
    for (int e = t; e < H_*32; e += 512){
        int j = e >> 5, bb = e & 31;
        sm7[GRN_H0 + e] = g_z[bb*H_ + j];
    }
    cluster_sync();

    const __half* gxk = g_gxnet_h + (long long)k*2048*G_;
    int cur = 0;

    for (int s = 0; s < 64; s++){
        float* h_cur = sm7 + (cur ? GRN_H1 : GRN_H0);
        float* h_nxt = sm7 + (cur ? GRN_H0 : GRN_H1);

        if (t < 226){
            int cp = t >> 1, pg = t & 1;   // col pair (2cp, 2cp+1), batch half pg
            int col0 = 2*cp, col1 = 2*cp + 1;
            unsigned long long acc[16];
            #pragma unroll
            for (int p = 0; p < 16; p++) acc[p] = 0ull;
            const float2* wp2 = (const float2*)w_sh + cp;
            const float* hb = h_cur + pg*16;
            #pragma unroll 2
            for (int i = 0; i < H_; i++){
                float2 w = wp2[i*113];
                unsigned long long w20 = pk2(w.x, w.x);
                unsigned long long w21 = pk2(w.y, w.y);
                const ulonglong2* hp = (const ulonglong2*)(hb + i*32);
                ulonglong2 q0 = hp[0], q1 = hp[1], q2 = hp[2], q3 = hp[3];
                fma2(acc[0],  w20, q0.x); fma2(acc[1],  w20, q0.y);
                fma2(acc[2],  w20, q1.x); fma2(acc[3],  w20, q1.y);
                fma2(acc[4],  w20, q2.x); fma2(acc[5],  w20, q2.y);
                fma2(acc[6],  w20, q3.x); fma2(acc[7],  w20, q3.y);
                fma2(acc[8],  w21, q0.x); fma2(acc[9],  w21, q0.y);
                fma2(acc[10], w21, q1.x); fma2(acc[11], w21, q1.y);
                fma2(acc[12], w21, q2.x); fma2(acc[13], w21, q2.y);
                fma2(acc[14], w21, q3.x); fma2(acc[15], w21, q3.y);
            }
            float bh0 = bhh_sh[col0];
            float bh1 = bhh_sh[col1];
            #pragma unroll
            for (int p = 0; p < 8; p++){
                float2 v0 = up2(acc[p]);
                float2 v1 = up2(acc[8 + p]);
                int bbA = pg*16 + 2*p, bbB = bbA + 1;
                gh_sh[bbA*228 + col0] = v0.x + bh0;
                gh_sh[bbB*228 + col0] = v0.y + bh0;
                gh_sh[bbA*228 + col1] = v1.x + bh1;
                gh_sh[bbB*228 + col1] = v1.y + bh1;
            }
        }
        __syncthreads();

        // update 75 h-rows x 32 batches; b64 local + peer pushes
        #pragma unroll
        for (int u = 0; u < 3; u++){
            int e = t + u*512;
            if (e < 1200){
                int jj = e >> 4, bbp = e & 15;
                int bb0 = bbp*2;
                int j = (int)hf*75 + jj;
                const __half* gx0 = gxk + (long long)(s*B_ + bb0)*G_ + j;
                const __half* gx1 = gx0 + G_;
                float ghr0 = gh_sh[bb0*228 + jj];
                float ghz0 = gh_sh[bb0*228 + 75  + jj];
                float ghn0 = gh_sh[bb0*228 + 150 + jj];
                float ghr1 = gh_sh[(bb0+1)*228 + jj];
                float ghz1 = gh_sh[(bb0+1)*228 + 75  + jj];
                float ghn1 = gh_sh[(bb0+1)*228 + 150 + jj];
                float r0  = sigf(__half2float(gx0[0])    + ghr0);
                float zz0 = sigf(__half2float(gx0[H_])   + ghz0);
                float n0  = tanhf_(__half2float(gx0[2*H_]) + r0*ghn0);
                float r1  = sigf(__half2float(gx1[0])    + ghr1);
                float zz1 = sigf(__half2float(gx1[H_])   + ghz1);
                float n1  = tanhf_(__half2float(gx1[2*H_]) + r1*ghn1);
                float h0o = h_cur[j*32 + bb0];
                float h1o = h_cur[j*32 + bb0 + 1];
                float hn0 = (1.f - zz0)*n0 + zz0*h0o;
                float hn1 = (1.f - zz1)*n1 + zz1*h1o;
                unsigned long long pv = pk2(hn0, hn1);
                *(unsigned long long*)&h_nxt[j*32 + bb0] = pv;
                st_peer_f64(&h_nxt[j*32 + bb0], peer, pv);
            }
        }
        cluster_sync();
        cur ^= 1;
    }

    float* hfin = sm7 + (cur ? GRN_H1 : GRN_H0);
    #pragma unroll
    for (int u = 0; u < 5; u++){
        int e = t + u*512;
        if (e < 2400){
            int bb = e / 75, jj = e - bb*75;
            int j = (int)hf*75 + jj;
            out[bb*(K_*H_) + k*H_ + j] = hfin[j*32 + bb];
        }
    }
}

// ---------------- launch ----------------
extern "C" void kernel_launch(void* const* d_in, const int* in_sizes, int n_in,
                              void* d_out, int out_size)
{
    const float* x       = (const float*)d_in[0];
    const float* y       = (const float*)d_in[1];
    const float* z_noise = (const float*)d_in[2];
    const float* lin_w   = (const float*)d_in[3];
    const float* lin_b   = (const float*)d_in[4];
    const float* a       = (const float*)d_in[5];
    const float* bias    = (const float*)d_in[6];
    const float* gl_wih  = (const float*)d_in[7];
    const float* gl_whh  = (const float*)d_in[8];
    const float* gl_bih  = (const float*)d_in[9];
    const float* gl_bhh  = (const float*)d_in[10];
    const float* mu_w    = (const float*)d_in[11];
    const float* mu_b    = (const float*)d_in[12];
    const float* std_w   = (const float*)d_in[13];
    const float* std_b   = (const float*)d_in[14];
    const float* net_wih = (const float*)d_in[15];
    const float* net_whh = (const float*)d_in[16];
    const float* net_bih = (const float*)d_in[17];
    const float* net_bhh = (const float*)d_in[18];
    float* out = (float*)d_out;

    static cudaStream_t s_side = nullptr;
    static cudaEvent_t ev1 = nullptr, ev2 = nullptr;
    if (!s_side){
        cudaStreamCreateWithFlags(&s_side, cudaStreamNonBlocking);
        cudaEventCreateWithFlags(&ev1, cudaEventDisableTiming);
        cudaEventCreateWithFlags(&ev2, cudaEventDisableTiming);
        cudaFuncSetAttribute(k_gxnet,   cudaFuncAttributeMaxDynamicSharedMemorySize,
                             GXN_SMEM_FLOATS*4);
        cudaFuncSetAttribute(k_gru_net, cudaFuncAttributeMaxDynamicSharedMemorySize,
                             GRN_SMEM_FLOATS*4);
        cudaFuncSetAttribute(k_gru_gl,  cudaFuncAttributeMaxDynamicSharedMemorySize,
                             GL_SMEM_FLOATS*4);
    }

    k_prep<<<256, 256>>>(lin_w, gl_wih, gl_whh, mu_w, std_w);     // idx 0
    k_wx<<<B_*K_, 128>>>(x, lin_b);                               // idx 1

    cudaEventRecord(ev1, 0);
    cudaStreamWaitEvent(s_side, ev1, 0);
    k_attn<<<B_*K_, 256, 0, s_side>>>(y, a, bias);                // idx 2

    k_gxnet<<<K_*2, 512, GXN_SMEM_FLOATS*4>>>(net_wih, net_bih);  // idx 3 <- profiled

    k_gxg<<<K_*B_, 512, 0, s_side>>>(gl_bih);
    k_gru_gl<<<B_*2, 256, GL_SMEM_FLOATS*4, s_side>>>(gl_bhh);
    k_z<<<B_, 160, 0, s_side>>>(mu_b, std_b, z_noise);
    cudaEventRecord(ev2, s_side);

    cudaStreamWaitEvent(0, ev2, 0);
    k_gru_net<<<K_*2, 512, GRN_SMEM_FLOATS*4>>>(net_whh, net_bhh, out);
}